// round 8
// baseline (speedup 1.0000x reference)
#include <cuda_runtime.h>
#include <cstdint>

// prediction [16,16,16,2048,10] fp32; label [2048] int32 (JAX x64 off).
// Output scalar fp32 = fraction of slices where argmax_c pred == label[b].
#define NC 10
#define NB 2048
#define N_SLICES (16 * 16 * 16 * 2048)     // 8,388,608 = 2^23
#define TPB 256                             // 8 warps
#define CHUNK_SLICES 256                    // per block per chunk (1/thread)
#define F4_PER_CHUNK 640                    // 256*10/4
#define F4_PER_WARP 80                      // 32 slices * 10 floats / 4
#define F2_PER_WARP 160
#define NBUF 4                              // ring depth (3 in flight + 1 consuming)
#define NCHUNK (N_SLICES / CHUNK_SLICES)    // 32768
#define GRID 740                            // 148 SMs * 5 resident CTAs

__device__ unsigned int g_correct_count;    // zero at load; self-reset each run
__device__ unsigned int g_blocks_done;

__device__ __forceinline__ int argmax10(const float* __restrict__ v) {
    float best = v[0];
    int idx = 0;
#pragma unroll
    for (int c = 1; c < NC; c++) {
        if (v[c] > best) { best = v[c]; idx = c; }
    }
    return idx;
}

__device__ __forceinline__ void cp_async16(uint32_t smem_addr, const void* gptr) {
    asm volatile("cp.async.cg.shared.global [%0], [%1], 16;\n"
                 :: "r"(smem_addr), "l"(gptr));
}
__device__ __forceinline__ void cp_async_commit() {
    asm volatile("cp.async.commit_group;\n");
}
template <int N>
__device__ __forceinline__ void cp_async_wait() {
    asm volatile("cp.async.wait_group %0;\n" :: "n"(N));
}

__global__ __launch_bounds__(TPB) void accuracy_fused_kernel(
    const float* __restrict__ pred,
    const int* __restrict__ label,
    float* __restrict__ out)
{
    __shared__ float4 tile[NBUF][F4_PER_CHUNK];   // 4 x 10 KB, warp-partitioned
    __shared__ unsigned int warp_sums[TPB / 32];

    const int tid  = threadIdx.x;
    const int lane = tid & 31;
    const int wid  = tid >> 5;
    const int bid  = blockIdx.x;

    // This warp's staging region inside each ring buffer.
    uint32_t waddr[NBUF];
#pragma unroll
    for (int d = 0; d < NBUF; d++) {
        waddr[d] = (uint32_t)__cvta_generic_to_shared(&tile[d][wid * F4_PER_WARP]);
    }

    const float4* const gpred = reinterpret_cast<const float4*>(pred);

    // Prefetch helper pattern: warp region = 80 float4 (1280 B), 2.5 per lane.
    // lanes issue idx lane, 32+lane, and (lane<16) 64+lane.
    // Prologue: prefetch chunks bid, bid+GRID, bid+2*GRID (always valid:
    // bid + 2*740 < 32768). One commit each.
#pragma unroll
    for (int d = 0; d < 3; d++) {
        const long long g = bid + (long long)d * GRID;
        const float4* src = gpred + g * F4_PER_CHUNK + wid * F4_PER_WARP;
        cp_async16(waddr[d] + (uint32_t)lane * 16u,        src + lane);
        cp_async16(waddr[d] + (uint32_t)(32 + lane) * 16u, src + 32 + lane);
        if (lane < 16)
            cp_async16(waddr[d] + (uint32_t)(64 + lane) * 16u, src + 64 + lane);
        cp_async_commit();
    }

    // Labels for this thread: batch = ((g&7)*256 + wid*32 + lane); preload all 8.
    int lab[8];
#pragma unroll
    for (int q = 0; q < 8; q++) {
        lab[q] = label[q * CHUNK_SLICES + wid * 32 + lane];
    }

    unsigned int my_correct = 0;

    int iter = 0;
    for (long long gc = bid; gc < NCHUNK; gc += GRID, iter++) {
        // Prefetch 3 chunks ahead into the buffer being freed this iteration.
        const long long gp = gc + 3LL * GRID;
        const int pbuf = (iter + 3) & (NBUF - 1);
        if (gp < NCHUNK) {
            const float4* src = gpred + gp * F4_PER_CHUNK + wid * F4_PER_WARP;
            cp_async16(waddr[pbuf] + (uint32_t)lane * 16u,        src + lane);
            cp_async16(waddr[pbuf] + (uint32_t)(32 + lane) * 16u, src + 32 + lane);
            if (lane < 16)
                cp_async16(waddr[pbuf] + (uint32_t)(64 + lane) * 16u, src + 64 + lane);
        }
        cp_async_commit();          // exactly one group per iteration (may be empty)
        cp_async_wait<3>();         // oldest group (chunk gc) complete
        __syncwarp();               // all lanes' staged data visible warp-wide

        // Lane owns slice wid*32+lane of chunk gc: float2 [5*lane, 5*lane+5).
        const int cbuf = iter & (NBUF - 1);
        const float2* wt = reinterpret_cast<const float2*>(
            &tile[cbuf][wid * F4_PER_WARP]);
        float2 q0 = wt[5 * lane + 0];
        float2 q1 = wt[5 * lane + 1];
        float2 q2 = wt[5 * lane + 2];
        float2 q3 = wt[5 * lane + 3];
        float2 q4 = wt[5 * lane + 4];

        float v[NC] = { q0.x, q0.y, q1.x, q1.y, q2.x,
                        q2.y, q3.x, q3.y, q4.x, q4.y };
        const int im = argmax10(v);

        my_correct += (im == lab[(int)(gc & 7)]) ? 1u : 0u;

        __syncwarp();               // reads done before pbuf slot refilled next time
    }

    // Warp redux -> block reduce -> one atomic per block (740 total, exact).
    unsigned int warp_total = __reduce_add_sync(0xFFFFFFFFu, my_correct);
    if (lane == 0) warp_sums[wid] = warp_total;
    __syncthreads();

    if (tid == 0) {
        unsigned int s = 0;
#pragma unroll
        for (int w = 0; w < TPB / 32; w++) s += warp_sums[w];
        atomicAdd(&g_correct_count, s);
        __threadfence();
        unsigned int done = atomicAdd(&g_blocks_done, 1u);
        if (done == GRID - 1) {
            unsigned int total = atomicAdd(&g_correct_count, 0u);   // L2 read
            out[0] = (float)total * (1.0f / (float)N_SLICES);       // exact /2^23
            g_correct_count = 0u;                                   // replay-safe
            g_blocks_done = 0u;
            __threadfence();
        }
    }
}

extern "C" void kernel_launch(void* const* d_in, const int* in_sizes, int n_in,
                              void* d_out, int out_size) {
    const float* pred = (const float*)d_in[0];
    const int* label = (const int*)d_in[1];
    float* out = (float*)d_out;

    accuracy_fused_kernel<<<GRID, TPB>>>(pred, label, out);
}

// round 9
// speedup vs baseline: 1.1099x; 1.1099x over previous
#include <cuda_runtime.h>
#include <cstdint>

// prediction [16,16,16,2048,10] fp32; label [2048] int32 (JAX x64 off).
// Output scalar fp32 = fraction of slices where argmax_c pred == label[b].
//
// At 6.3 TB/s this kernel sits on the B300 LTS fabric cap (path-independent);
// structure: warp-private depth-2 cp.async pipeline, 512-slice chunks,
// 4 chunks per CTA for fine-grained tail balance.
#define NC 10
#define NB 2048
#define N_SLICES (16 * 16 * 16 * 2048)        // 8,388,608 = 2^23
#define TPB 256                                // 8 warps
#define CHUNK_SLICES 512                       // per block per chunk (2/thread)
#define F4_PER_CHUNK (CHUNK_SLICES * NC / 4)   // 1280 float4 = 20 KB
#define SLICES_PER_WARP 64                     // per chunk
#define F4_PER_WARP 160                        // 64*10/4
#define F4_PER_LANE 5
#define CHUNKS_PER_BLOCK 4
#define GRID (N_SLICES / (CHUNK_SLICES * CHUNKS_PER_BLOCK))   // 4096 blocks

__device__ unsigned int g_correct_count;   // zero at load; self-reset each run
__device__ unsigned int g_blocks_done;

__device__ __forceinline__ int argmax10(const float* __restrict__ v) {
    float best = v[0];
    int idx = 0;
#pragma unroll
    for (int c = 1; c < NC; c++) {
        if (v[c] > best) { best = v[c]; idx = c; }
    }
    return idx;
}

__device__ __forceinline__ void cp_async16(uint32_t smem_addr, const void* gptr) {
    asm volatile("cp.async.cg.shared.global [%0], [%1], 16;\n"
                 :: "r"(smem_addr), "l"(gptr));
}
__device__ __forceinline__ void cp_async_commit() {
    asm volatile("cp.async.commit_group;\n");
}
template <int N>
__device__ __forceinline__ void cp_async_wait() {
    asm volatile("cp.async.wait_group %0;\n" :: "n"(N));
}

__global__ __launch_bounds__(TPB) void accuracy_fused_kernel(
    const float* __restrict__ pred,
    const int* __restrict__ label,
    float* __restrict__ out)
{
    __shared__ float4 tile[2][F4_PER_CHUNK];   // 2 x 20 KB, warp-partitioned
    __shared__ unsigned int warp_sums[TPB / 32];

    const int tid  = threadIdx.x;
    const int lane = tid & 31;
    const int wid  = tid >> 5;
    const long long chunk0 = (long long)blockIdx.x * CHUNKS_PER_BLOCK;   // mult of 4

    // This warp's staging regions.
    float4* const wtile0 = &tile[0][wid * F4_PER_WARP];
    float4* const wtile1 = &tile[1][wid * F4_PER_WARP];
    const uint32_t waddr0 = (uint32_t)__cvta_generic_to_shared(wtile0);
    const uint32_t waddr1 = (uint32_t)__cvta_generic_to_shared(wtile1);

    // Global base for this warp's slice stream (float4 units).
    const float4* const gbase = reinterpret_cast<const float4*>(pred)
                              + chunk0 * F4_PER_CHUNK + wid * F4_PER_WARP;

    // Batch index of this thread's 2 slices in chunk c:
    //   ((chunk0+c)*512 + wid*64 + 2*lane) mod 2048; chunk0 mod 4 == 0
    //   -> (c mod 4)*512 + wid*64 + 2*lane. Preload all 4 label pairs.
    int lab0[4], lab1[4];
#pragma unroll
    for (int q = 0; q < 4; q++) {
        int2 lp = *reinterpret_cast<const int2*>(
            label + (q * CHUNK_SLICES + wid * SLICES_PER_WARP + 2 * lane));
        lab0[q] = lp.x;
        lab1[q] = lp.y;
    }

    unsigned int my_correct = 0;

    // Prefetch chunk 0 into buf 0 (warp-private; 5 coalesced 16B cp.async/lane).
#pragma unroll
    for (int j = 0; j < F4_PER_LANE; j++) {
        cp_async16(waddr0 + (uint32_t)(j * 32 + lane) * 16u,
                   gbase + j * 32 + lane);
    }
    cp_async_commit();

#pragma unroll
    for (int c = 0; c < CHUNKS_PER_BLOCK; c++) {
        const int cur = c & 1;
        if (c + 1 < CHUNKS_PER_BLOCK) {
            const float4* src = gbase + (long long)(c + 1) * F4_PER_CHUNK;
            const uint32_t nxt_addr = cur ? waddr0 : waddr1;
#pragma unroll
            for (int j = 0; j < F4_PER_LANE; j++) {
                cp_async16(nxt_addr + (uint32_t)(j * 32 + lane) * 16u,
                           src + j * 32 + lane);
            }
            cp_async_commit();
            cp_async_wait<1>();   // current chunk's group complete (this lane)
        } else {
            cp_async_wait<0>();
        }
        __syncwarp();             // warp's staged data visible to all lanes

        // Lane owns slices 2*lane, 2*lane+1 of the warp's 64:
        // float4 [5*lane, 5*lane+5). 80 B/lane stride -> conflict-free LDS.128.
        const float4* wt = cur ? wtile1 : wtile0;
        float4 q[5];
#pragma unroll
        for (int j = 0; j < 5; j++) q[j] = wt[5 * lane + j];

        float a[NC] = { q[0].x, q[0].y, q[0].z, q[0].w,
                        q[1].x, q[1].y, q[1].z, q[1].w,
                        q[2].x, q[2].y };
        float b[NC] = { q[2].z, q[2].w,
                        q[3].x, q[3].y, q[3].z, q[3].w,
                        q[4].x, q[4].y, q[4].z, q[4].w };

        const int i0 = argmax10(a);
        const int i1 = argmax10(b);

        const int qsel = c & 3;
        my_correct += (i0 == lab0[qsel]) ? 1u : 0u;
        my_correct += (i1 == lab1[qsel]) ? 1u : 0u;

        __syncwarp();             // reads done before this buffer is re-filled
    }

    // Warp redux -> block reduce -> one atomic per block (4096 total, exact).
    unsigned int warp_total = __reduce_add_sync(0xFFFFFFFFu, my_correct);
    if (lane == 0) warp_sums[wid] = warp_total;
    __syncthreads();

    if (tid == 0) {
        unsigned int s = 0;
#pragma unroll
        for (int w = 0; w < TPB / 32; w++) s += warp_sums[w];
        atomicAdd(&g_correct_count, s);
        __threadfence();
        unsigned int done = atomicAdd(&g_blocks_done, 1u);
        if (done == GRID - 1) {
            unsigned int total = atomicAdd(&g_correct_count, 0u);   // L2 read
            out[0] = (float)total * (1.0f / (float)N_SLICES);       // exact /2^23
            g_correct_count = 0u;                                   // replay-safe
            g_blocks_done = 0u;
            __threadfence();
        }
    }
}

extern "C" void kernel_launch(void* const* d_in, const int* in_sizes, int n_in,
                              void* d_out, int out_size) {
    const float* pred = (const float*)d_in[0];
    const int* label = (const int*)d_in[1];
    float* out = (float*)d_out;

    accuracy_fused_kernel<<<GRID, TPB>>>(pred, label, out);
}